// round 4
// baseline (speedup 1.0000x reference)
#include <cuda_runtime.h>
#include <cuda_fp16.h>
#include <cstdint>

// ---------------------------------------------------------------------------
// KipfAndWellingConv: out = segment_sum(w_e * (x @ F)[src_e], dst_e)
//   x [100000,128] f32, filters [128,128] f32,
//   edge_src/edge_dst [3.2M] int32 (dst sorted), edge_weight f32
//   out [100000,128] f32
// R4: XF stored fp16 (halves L2 gather traffic), zero fused into GEMM,
//     batched MLP=8 gathers, plain-store flush for warp-owned segments.
// ---------------------------------------------------------------------------

#define NF 128
#define EPW 128              // edges per warp in aggregation
#define TILE 8               // gather batch (MLP per warp)

__device__ __half g_XFh[100000 * NF];   // XF scratch, fp16 (25.6 MB)

// ---------------------------------------------------------------------------
__device__ __forceinline__ float to_tf32(float x)
{
    float r;
    asm("cvt.rna.tf32.f32 %0, %1;" : "=f"(r) : "f"(x));
    return r;
}

__device__ __forceinline__ void mma_tf32(float* d, const uint32_t* a, const uint32_t* b)
{
    asm volatile(
        "mma.sync.aligned.m16n8k8.row.col.f32.tf32.tf32.f32 "
        "{%0,%1,%2,%3}, {%4,%5,%6,%7}, {%8,%9}, {%0,%1,%2,%3};\n"
        : "+f"(d[0]), "+f"(d[1]), "+f"(d[2]), "+f"(d[3])
        : "r"(a[0]), "r"(a[1]), "r"(a[2]), "r"(a[3]), "r"(b[0]), "r"(b[1]));
}

// GEMM: XF[M,128] = X[M,128] @ F[128,128], tf32 tensor cores, fp16 output.
// Also zero-fills `out` (grid-stride) so no separate zero kernel is needed.
__global__ __launch_bounds__(256)
void gemm_tf32(const float* __restrict__ X, const float* __restrict__ F, int M,
               float4* __restrict__ out4, int n4)
{
    __shared__ float As[64][36];
    __shared__ float Bs[32][136];

    // fused zero of the output (independent of the GEMM work)
    for (int i = blockIdx.x * blockDim.x + threadIdx.x; i < n4;
         i += gridDim.x * blockDim.x)
        out4[i] = make_float4(0.f, 0.f, 0.f, 0.f);

    const int tid  = threadIdx.x;
    const int row0 = blockIdx.x * 64;
    const int wid  = tid >> 5;
    const int lane = tid & 31;
    const int g    = lane >> 2;
    const int t    = lane & 3;
    const int wm0  = (wid >> 2) * 32;
    const int wn0  = (wid & 3) * 32;

    float d[2][4][4];
#pragma unroll
    for (int i = 0; i < 2; ++i)
#pragma unroll
        for (int j = 0; j < 4; ++j)
#pragma unroll
            for (int k = 0; k < 4; ++k) d[i][j][k] = 0.f;

    for (int kt = 0; kt < 4; ++kt) {
#pragma unroll
        for (int p = 0; p < 2; ++p) {
            int i4 = tid + p * 256;
            int r  = i4 >> 3;
            int c  = (i4 & 7) * 4;
            float4 v = make_float4(0.f, 0.f, 0.f, 0.f);
            int grow = row0 + r;
            if (grow < M)
                v = *(const float4*)(X + (size_t)grow * NF + kt * 32 + c);
            v.x = to_tf32(v.x); v.y = to_tf32(v.y);
            v.z = to_tf32(v.z); v.w = to_tf32(v.w);
            *(float4*)&As[r][c] = v;
        }
#pragma unroll
        for (int p = 0; p < 4; ++p) {
            int i4 = tid + p * 256;
            int r  = i4 >> 5;
            int c  = (i4 & 31) * 4;
            float4 v = *(const float4*)(F + (size_t)(kt * 32 + r) * NF + c);
            v.x = to_tf32(v.x); v.y = to_tf32(v.y);
            v.z = to_tf32(v.z); v.w = to_tf32(v.w);
            *(float4*)&Bs[r][c] = v;
        }
        __syncthreads();

#pragma unroll
        for (int k8 = 0; k8 < 4; ++k8) {
            const int kb = k8 * 8;
            uint32_t a[2][4], b[4][2];
#pragma unroll
            for (int im = 0; im < 2; ++im) {
                int rb = wm0 + im * 16 + g;
                a[im][0] = __float_as_uint(As[rb][kb + t]);
                a[im][1] = __float_as_uint(As[rb + 8][kb + t]);
                a[im][2] = __float_as_uint(As[rb][kb + t + 4]);
                a[im][3] = __float_as_uint(As[rb + 8][kb + t + 4]);
            }
#pragma unroll
            for (int jn = 0; jn < 4; ++jn) {
                int cb = wn0 + jn * 8 + g;
                b[jn][0] = __float_as_uint(Bs[kb + t][cb]);
                b[jn][1] = __float_as_uint(Bs[kb + t + 4][cb]);
            }
#pragma unroll
            for (int im = 0; im < 2; ++im)
#pragma unroll
                for (int jn = 0; jn < 4; ++jn)
                    mma_tf32(d[im][jn], a[im], b[jn]);
        }
        __syncthreads();
    }

    // Epilogue -> fp16
#pragma unroll
    for (int im = 0; im < 2; ++im) {
#pragma unroll
        for (int half = 0; half < 2; ++half) {
            int grow = row0 + wm0 + im * 16 + half * 8 + g;
            if (grow < M) {
#pragma unroll
                for (int jn = 0; jn < 4; ++jn) {
                    float2 v = make_float2(d[im][jn][half * 2],
                                           d[im][jn][half * 2 + 1]);
                    __half2 h = __float22half2_rn(v);
                    *(__half2*)(g_XFh + (size_t)grow * NF + wn0 + jn * 8 + t * 2) = h;
                }
            }
        }
    }
}

// ---------------------------------------------------------------------------
// Aggregation: warp per EPW edges; batched TILE-deep gathers for MLP.
// Lane l owns features [4l,4l+4) = one uint2 (4 halves) of the fp16 row.
// dst sorted: register-accumulate; interior segments flushed with plain
// stores (exclusively owned), boundary segments with atomicAdd.
__global__ __launch_bounds__(256)
void agg_kernel(const int* __restrict__ src,
                const int* __restrict__ dst,
                const float* __restrict__ w,
                float* __restrict__ out, int E)
{
    const int gw   = (blockIdx.x * blockDim.x + threadIdx.x) >> 5;
    const int lane = threadIdx.x & 31;

    long long base = (long long)gw * EPW;
    if (base >= E) return;
    long long end = base + EPW;
    if (end > E) end = E;

    const uint2* __restrict__ XFr = (const uint2*)g_XFh;   // 32 uint2 per row

    float4 acc = make_float4(0.f, 0.f, 0.f, 0.f);
    int  cur   = dst[base];
    bool owned = false;      // current segment started inside this chunk?

    for (long long t0 = base; t0 < end; t0 += TILE) {
        uint2 v[TILE];
        float ww[TILE];
        int   dd[TILE];
#pragma unroll
        for (int j = 0; j < TILE; ++j) {
            long long e = t0 + j;
            if (e >= end) e = end - 1;      // clamped (redundant) loads
            int s  = src[e];
            dd[j]  = dst[e];
            ww[j]  = w[e];
            v[j]   = XFr[(size_t)s * 32 + lane];
        }
#pragma unroll
        for (int j = 0; j < TILE; ++j) {
            if (t0 + j >= end) break;
            if (dd[j] != cur) {
                float* o = out + (size_t)cur * NF + lane * 4;
                if (owned) {
                    *(float4*)o = acc;       // exclusive segment
                } else {
                    atomicAdd(o + 0, acc.x);
                    atomicAdd(o + 1, acc.y);
                    atomicAdd(o + 2, acc.z);
                    atomicAdd(o + 3, acc.w);
                }
                acc   = make_float4(0.f, 0.f, 0.f, 0.f);
                cur   = dd[j];
                owned = true;                // new segment begins here
            }
            float2 lo = __half22float2(*(__half2*)&v[j].x);
            float2 hi = __half22float2(*(__half2*)&v[j].y);
            float  wt = ww[j];
            acc.x += wt * lo.x;
            acc.y += wt * lo.y;
            acc.z += wt * hi.x;
            acc.w += wt * hi.y;
        }
    }
    // final flush: segment may continue into the next chunk -> always atomic
    float* o = out + (size_t)cur * NF + lane * 4;
    atomicAdd(o + 0, acc.x);
    atomicAdd(o + 1, acc.y);
    atomicAdd(o + 2, acc.z);
    atomicAdd(o + 3, acc.w);
}

// ---------------------------------------------------------------------------
extern "C" void kernel_launch(void* const* d_in, const int* in_sizes, int n_in,
                              void* d_out, int out_size)
{
    const float* x    = (const float*)d_in[0];
    const float* f    = (const float*)d_in[1];
    const int*   esrc = (const int*)d_in[2];
    const int*   edst = (const int*)d_in[3];
    const float* ew   = (const float*)d_in[4];
    float*       out  = (float*)d_out;

    const int M = in_sizes[0] / NF;   // 100000
    const int E = in_sizes[2];        // 3200000

    int n4 = out_size / 4;
    gemm_tf32<<<(M + 63) / 64, 256>>>(x, f, M, (float4*)out, n4);

    int warps  = (E + EPW - 1) / EPW;
    int blocks = (warps * 32 + 255) / 256;
    agg_kernel<<<blocks, 256>>>(esrc, edst, ew, out, E);
}

// round 7
// speedup vs baseline: 1.4804x; 1.4804x over previous
#include <cuda_runtime.h>
#include <cuda_fp16.h>
#include <cstdint>

// ---------------------------------------------------------------------------
// KipfAndWellingConv: out = segment_sum(w_e * (x @ F)[src_e], dst_e)
// R5/R6/R7 (resubmit after infra timeouts): standalone tf32 GEMM (fp16 XF
// out), memsetAsync zero, low-instruction agg: lane-parallel metadata +
// ballot boundary mask + shfl broadcast.
// ---------------------------------------------------------------------------

#define NF 128
#define EPW 128              // edges per warp (3.2M % 128 == 0)
#define FULL 0xFFFFFFFFu

__device__ __half g_XFh[100000 * NF];   // XF scratch, fp16 (25.6 MB)

// ---------------------------------------------------------------------------
__device__ __forceinline__ float to_tf32(float x)
{
    float r;
    asm("cvt.rna.tf32.f32 %0, %1;" : "=f"(r) : "f"(x));
    return r;
}

__device__ __forceinline__ void mma_tf32(float* d, const uint32_t* a, const uint32_t* b)
{
    asm volatile(
        "mma.sync.aligned.m16n8k8.row.col.f32.tf32.tf32.f32 "
        "{%0,%1,%2,%3}, {%4,%5,%6,%7}, {%8,%9}, {%0,%1,%2,%3};\n"
        : "+f"(d[0]), "+f"(d[1]), "+f"(d[2]), "+f"(d[3])
        : "r"(a[0]), "r"(a[1]), "r"(a[2]), "r"(a[3]), "r"(b[0]), "r"(b[1]));
}

// GEMM: XF[M,128] = X[M,128] @ F[128,128], tf32 tensor cores, fp16 output.
__global__ __launch_bounds__(256)
void gemm_tf32(const float* __restrict__ X, const float* __restrict__ F, int M)
{
    __shared__ float As[64][36];
    __shared__ float Bs[32][136];

    const int tid  = threadIdx.x;
    const int row0 = blockIdx.x * 64;
    const int wid  = tid >> 5;
    const int lane = tid & 31;
    const int g    = lane >> 2;
    const int t    = lane & 3;
    const int wm0  = (wid >> 2) * 32;
    const int wn0  = (wid & 3) * 32;

    float d[2][4][4];
#pragma unroll
    for (int i = 0; i < 2; ++i)
#pragma unroll
        for (int j = 0; j < 4; ++j)
#pragma unroll
            for (int k = 0; k < 4; ++k) d[i][j][k] = 0.f;

    for (int kt = 0; kt < 4; ++kt) {
#pragma unroll
        for (int p = 0; p < 2; ++p) {
            int i4 = tid + p * 256;
            int r  = i4 >> 3;
            int c  = (i4 & 7) * 4;
            float4 v = make_float4(0.f, 0.f, 0.f, 0.f);
            int grow = row0 + r;
            if (grow < M)
                v = *(const float4*)(X + (size_t)grow * NF + kt * 32 + c);
            v.x = to_tf32(v.x); v.y = to_tf32(v.y);
            v.z = to_tf32(v.z); v.w = to_tf32(v.w);
            *(float4*)&As[r][c] = v;
        }
#pragma unroll
        for (int p = 0; p < 4; ++p) {
            int i4 = tid + p * 256;
            int r  = i4 >> 5;
            int c  = (i4 & 31) * 4;
            float4 v = *(const float4*)(F + (size_t)(kt * 32 + r) * NF + c);
            v.x = to_tf32(v.x); v.y = to_tf32(v.y);
            v.z = to_tf32(v.z); v.w = to_tf32(v.w);
            *(float4*)&Bs[r][c] = v;
        }
        __syncthreads();

#pragma unroll
        for (int k8 = 0; k8 < 4; ++k8) {
            const int kb = k8 * 8;
            uint32_t a[2][4], b[4][2];
#pragma unroll
            for (int im = 0; im < 2; ++im) {
                int rb = wm0 + im * 16 + g;
                a[im][0] = __float_as_uint(As[rb][kb + t]);
                a[im][1] = __float_as_uint(As[rb + 8][kb + t]);
                a[im][2] = __float_as_uint(As[rb][kb + t + 4]);
                a[im][3] = __float_as_uint(As[rb + 8][kb + t + 4]);
            }
#pragma unroll
            for (int jn = 0; jn < 4; ++jn) {
                int cb = wn0 + jn * 8 + g;
                b[jn][0] = __float_as_uint(Bs[kb + t][cb]);
                b[jn][1] = __float_as_uint(Bs[kb + t + 4][cb]);
            }
#pragma unroll
            for (int im = 0; im < 2; ++im)
#pragma unroll
                for (int jn = 0; jn < 4; ++jn)
                    mma_tf32(d[im][jn], a[im], b[jn]);
        }
        __syncthreads();
    }

#pragma unroll
    for (int im = 0; im < 2; ++im) {
#pragma unroll
        for (int half = 0; half < 2; ++half) {
            int grow = row0 + wm0 + im * 16 + half * 8 + g;
            if (grow < M) {
#pragma unroll
                for (int jn = 0; jn < 4; ++jn) {
                    float2 v = make_float2(d[im][jn][half * 2],
                                           d[im][jn][half * 2 + 1]);
                    __half2 h = __float22half2_rn(v);
                    *(__half2*)(g_XFh + (size_t)grow * NF + wn0 + jn * 8 + t * 2) = h;
                }
            }
        }
    }
}

// ---------------------------------------------------------------------------
__device__ __forceinline__ void flush_seg(float* __restrict__ out, int node,
                                          int lane, const float4& acc, bool owned)
{
    float* o = out + (size_t)node * NF + lane * 4;
    if (owned) {
        *(float4*)o = acc;
    } else {
        atomicAdd(o + 0, acc.x);
        atomicAdd(o + 1, acc.y);
        atomicAdd(o + 2, acc.z);
        atomicAdd(o + 3, acc.w);
    }
}

// Aggregation: warp per EPW edges. Per 32-edge batch: lane j holds edge j's
// (src, dst, w); boundary mask from ballot(shfl_up); hot loop = 1 shfl(src)
// + 1 LDG.64 gather + 1 shfl(w) + mask-bit test + 2 cvt + 4 FFMA.
__global__ __launch_bounds__(256)
void agg_kernel(const int* __restrict__ src,
                const int* __restrict__ dst,
                const float* __restrict__ w,
                float* __restrict__ out, int E)
{
    const int gw   = (blockIdx.x * blockDim.x + threadIdx.x) >> 5;
    const int lane = threadIdx.x & 31;

    const long long base = (long long)gw * EPW;
    if (base >= E) return;

    const uint2* __restrict__ XFr = (const uint2*)g_XFh;   // 32 uint2 / row

    float4 acc = make_float4(0.f, 0.f, 0.f, 0.f);
    int  cur   = dst[base];
    bool owned = false;
    int  prev_last = cur;

    if (base + EPW <= E) {
        // ---- hot path: full chunk, no tail checks ----
#pragma unroll 1
        for (int b = 0; b < EPW / 32; ++b) {
            const long long t0 = base + b * 32;
            int   s_r = src[t0 + lane];
            int   d_r = dst[t0 + lane];
            float w_r = w[t0 + lane];

            int dprev = __shfl_up_sync(FULL, d_r, 1);
            if (lane == 0) dprev = prev_last;
            unsigned bmask = __ballot_sync(FULL, d_r != dprev);
            prev_last = __shfl_sync(FULL, d_r, 31);

#pragma unroll
            for (int q = 0; q < 4; ++q) {
                uint2 v[8];
#pragma unroll
                for (int j = 0; j < 8; ++j) {
                    int sj = __shfl_sync(FULL, s_r, q * 8 + j);
                    v[j] = __ldg(&XFr[(unsigned)sj * 32u + lane]);
                }
#pragma unroll
                for (int j = 0; j < 8; ++j) {
                    const int e = q * 8 + j;
                    if (bmask & (1u << e)) {
                        flush_seg(out, cur, lane, acc, owned);
                        acc   = make_float4(0.f, 0.f, 0.f, 0.f);
                        owned = true;
                        cur   = __shfl_sync(FULL, d_r, e);
                    }
                    float wt  = __shfl_sync(FULL, w_r, e);
                    float2 lo = __half22float2(*(__half2*)&v[j].x);
                    float2 hi = __half22float2(*(__half2*)&v[j].y);
                    acc.x += wt * lo.x;
                    acc.y += wt * lo.y;
                    acc.z += wt * hi.x;
                    acc.w += wt * hi.y;
                }
            }
        }
    } else {
        // ---- cold tail path: serial ----
        long long end = E;
        for (long long e = base; e < end; ++e) {
            int   d  = dst[e];
            if (d != cur) {
                flush_seg(out, cur, lane, acc, owned);
                acc   = make_float4(0.f, 0.f, 0.f, 0.f);
                owned = true;
                cur   = d;
            }
            uint2  v  = XFr[(unsigned)src[e] * 32u + lane];
            float  wt = w[e];
            float2 lo = __half22float2(*(__half2*)&v.x);
            float2 hi = __half22float2(*(__half2*)&v.y);
            acc.x += wt * lo.x;
            acc.y += wt * lo.y;
            acc.z += wt * hi.x;
            acc.w += wt * hi.y;
        }
    }

    // final flush: may continue into next chunk -> atomic
    float* o = out + (size_t)cur * NF + lane * 4;
    atomicAdd(o + 0, acc.x);
    atomicAdd(o + 1, acc.y);
    atomicAdd(o + 2, acc.z);
    atomicAdd(o + 3, acc.w);
}

// ---------------------------------------------------------------------------
extern "C" void kernel_launch(void* const* d_in, const int* in_sizes, int n_in,
                              void* d_out, int out_size)
{
    const float* x    = (const float*)d_in[0];
    const float* f    = (const float*)d_in[1];
    const int*   esrc = (const int*)d_in[2];
    const int*   edst = (const int*)d_in[3];
    const float* ew   = (const float*)d_in[4];
    float*       out  = (float*)d_out;

    const int M = in_sizes[0] / NF;   // 100000
    const int E = in_sizes[2];        // 3200000

    cudaMemsetAsync(d_out, 0, (size_t)out_size * sizeof(float), 0);

    gemm_tf32<<<(M + 63) / 64, 256>>>(x, f, M);

    int warps  = (E + EPW - 1) / EPW;
    int blocks = (warps * 32 + 255) / 256;
    agg_kernel<<<blocks, 256>>>(esrc, edst, ew, out, E);
}

// round 13
// speedup vs baseline: 1.7073x; 1.1533x over previous
#include <cuda_runtime.h>
#include <cuda_fp16.h>
#include <cstdint>

// ---------------------------------------------------------------------------
// KipfAndWellingConv: out = segment_sum(w_e * (x @ F)[src_e], dst_e)
// R8..R13 (resubmit; broker timeouts): GEMM gets cp.async double-buffered
// k-pipeline (RNA cvt moved to fragments); agg flushes use
// red.global.add.v4.f32.
// ---------------------------------------------------------------------------

#define NF 128
#define EPW 128              // edges per warp (3.2M % 128 == 0)
#define FULL 0xFFFFFFFFu

__device__ __half g_XFh[100000 * NF];   // XF scratch, fp16 (25.6 MB)

// ---------------------------------------------------------------------------
__device__ __forceinline__ float to_tf32(float x)
{
    float r;
    asm("cvt.rna.tf32.f32 %0, %1;" : "=f"(r) : "f"(x));
    return r;
}

__device__ __forceinline__ void mma_tf32(float* d, const uint32_t* a, const uint32_t* b)
{
    asm volatile(
        "mma.sync.aligned.m16n8k8.row.col.f32.tf32.tf32.f32 "
        "{%0,%1,%2,%3}, {%4,%5,%6,%7}, {%8,%9}, {%0,%1,%2,%3};\n"
        : "+f"(d[0]), "+f"(d[1]), "+f"(d[2]), "+f"(d[3])
        : "r"(a[0]), "r"(a[1]), "r"(a[2]), "r"(a[3]), "r"(b[0]), "r"(b[1]));
}

__device__ __forceinline__ void cp16(uint32_t smem_addr, const void* gptr, bool pred)
{
    asm volatile("cp.async.ca.shared.global [%0], [%1], 16, %2;\n"
                 :: "r"(smem_addr), "l"(gptr), "r"(pred ? 16 : 0));
}
__device__ __forceinline__ void cp_commit()
{
    asm volatile("cp.async.commit_group;\n");
}
template <int N>
__device__ __forceinline__ void cp_wait()
{
    asm volatile("cp.async.wait_group %0;\n" :: "n"(N));
}

// GEMM: XF[M,128] = X[M,128] @ F[128,128], tf32 tensor cores, fp16 output.
// 2-stage cp.async pipeline over 4 k-tiles; RNA tf32 cvt applied to frags.
__global__ __launch_bounds__(256)
void gemm_tf32(const float* __restrict__ X, const float* __restrict__ F, int M)
{
    __shared__ float As[2][64][36];
    __shared__ float Bs[2][32][136];

    const int tid  = threadIdx.x;
    const int row0 = blockIdx.x * 64;
    const int wid  = tid >> 5;
    const int lane = tid & 31;
    const int g    = lane >> 2;
    const int t    = lane & 3;
    const int wm0  = (wid >> 2) * 32;
    const int wn0  = (wid & 3) * 32;

    // per-thread load coordinates (fixed across stages)
    const int ar0 = (tid + 0)   >> 3, ac0 = ((tid + 0)   & 7) * 4;
    const int ar1 = (tid + 256) >> 3, ac1 = ((tid + 256) & 7) * 4;

    auto load_stage = [&](int kt, int buf) {
        // A tile: 64 x 32 (2 x 16B per thread)
        cp16(__cvta_generic_to_shared(&As[buf][ar0][ac0]),
             X + (size_t)(row0 + ar0) * NF + kt * 32 + ac0, row0 + ar0 < M);
        cp16(__cvta_generic_to_shared(&As[buf][ar1][ac1]),
             X + (size_t)(row0 + ar1) * NF + kt * 32 + ac1, row0 + ar1 < M);
        // B tile: 32 x 128 (4 x 16B per thread)
#pragma unroll
        for (int p = 0; p < 4; ++p) {
            int i4 = tid + p * 256;
            int r  = i4 >> 5;
            int c  = (i4 & 31) * 4;
            cp16(__cvta_generic_to_shared(&Bs[buf][r][c]),
                 F + (size_t)(kt * 32 + r) * NF + c, true);
        }
    };

    float d[2][4][4];
#pragma unroll
    for (int i = 0; i < 2; ++i)
#pragma unroll
        for (int j = 0; j < 4; ++j)
#pragma unroll
            for (int k = 0; k < 4; ++k) d[i][j][k] = 0.f;

    load_stage(0, 0);
    cp_commit();

    for (int kt = 0; kt < 4; ++kt) {
        const int buf = kt & 1;
        if (kt < 3) {
            load_stage(kt + 1, buf ^ 1);
            cp_commit();
            cp_wait<1>();
        } else {
            cp_wait<0>();
        }
        __syncthreads();

#pragma unroll
        for (int k8 = 0; k8 < 4; ++k8) {
            const int kb = k8 * 8;
            uint32_t a[2][4], b[4][2];
#pragma unroll
            for (int im = 0; im < 2; ++im) {
                int rb = wm0 + im * 16 + g;
                a[im][0] = __float_as_uint(to_tf32(As[buf][rb][kb + t]));
                a[im][1] = __float_as_uint(to_tf32(As[buf][rb + 8][kb + t]));
                a[im][2] = __float_as_uint(to_tf32(As[buf][rb][kb + t + 4]));
                a[im][3] = __float_as_uint(to_tf32(As[buf][rb + 8][kb + t + 4]));
            }
#pragma unroll
            for (int jn = 0; jn < 4; ++jn) {
                int cb = wn0 + jn * 8 + g;
                b[jn][0] = __float_as_uint(to_tf32(Bs[buf][kb + t][cb]));
                b[jn][1] = __float_as_uint(to_tf32(Bs[buf][kb + t + 4][cb]));
            }
#pragma unroll
            for (int im = 0; im < 2; ++im)
#pragma unroll
                for (int jn = 0; jn < 4; ++jn)
                    mma_tf32(d[im][jn], a[im], b[jn]);
        }
        __syncthreads();
    }

#pragma unroll
    for (int im = 0; im < 2; ++im) {
#pragma unroll
        for (int half = 0; half < 2; ++half) {
            int grow = row0 + wm0 + im * 16 + half * 8 + g;
            if (grow < M) {
#pragma unroll
                for (int jn = 0; jn < 4; ++jn) {
                    float2 v = make_float2(d[im][jn][half * 2],
                                           d[im][jn][half * 2 + 1]);
                    __half2 h = __float22half2_rn(v);
                    *(__half2*)(g_XFh + (size_t)grow * NF + wn0 + jn * 8 + t * 2) = h;
                }
            }
        }
    }
}

// ---------------------------------------------------------------------------
__device__ __forceinline__ void red_v4(float* o, const float4& a)
{
    asm volatile("red.global.add.v4.f32 [%0], {%1, %2, %3, %4};\n"
                 :: "l"(o), "f"(a.x), "f"(a.y), "f"(a.z), "f"(a.w) : "memory");
}

__device__ __forceinline__ void flush_seg(float* __restrict__ out, int node,
                                          int lane, const float4& acc, bool owned)
{
    float* o = out + (size_t)node * NF + lane * 4;
    if (owned) {
        *(float4*)o = acc;          // exclusive interior segment
    } else {
        red_v4(o, acc);             // one REDG.128 per lane
    }
}

// Aggregation: warp per EPW edges; lane-parallel metadata, ballot boundary
// mask, shfl broadcast, 8-deep gather batches, vectorized reduction flushes.
__global__ __launch_bounds__(256)
void agg_kernel(const int* __restrict__ src,
                const int* __restrict__ dst,
                const float* __restrict__ w,
                float* __restrict__ out, int E)
{
    const int gw   = (blockIdx.x * blockDim.x + threadIdx.x) >> 5;
    const int lane = threadIdx.x & 31;

    const long long base = (long long)gw * EPW;
    if (base >= E) return;

    const uint2* __restrict__ XFr = (const uint2*)g_XFh;   // 32 uint2 / row

    float4 acc = make_float4(0.f, 0.f, 0.f, 0.f);
    int  cur   = dst[base];
    bool owned = false;
    int  prev_last = cur;

    if (base + EPW <= E) {
#pragma unroll 1
        for (int b = 0; b < EPW / 32; ++b) {
            const long long t0 = base + b * 32;
            int   s_r = src[t0 + lane];
            int   d_r = dst[t0 + lane];
            float w_r = w[t0 + lane];

            int dprev = __shfl_up_sync(FULL, d_r, 1);
            if (lane == 0) dprev = prev_last;
            unsigned bmask = __ballot_sync(FULL, d_r != dprev);
            prev_last = __shfl_sync(FULL, d_r, 31);

#pragma unroll
            for (int q = 0; q < 4; ++q) {
                uint2 v[8];
#pragma unroll
                for (int j = 0; j < 8; ++j) {
                    int sj = __shfl_sync(FULL, s_r, q * 8 + j);
                    v[j] = __ldg(&XFr[(unsigned)sj * 32u + lane]);
                }
#pragma unroll
                for (int j = 0; j < 8; ++j) {
                    const int e = q * 8 + j;
                    if (bmask & (1u << e)) {
                        flush_seg(out, cur, lane, acc, owned);
                        acc   = make_float4(0.f, 0.f, 0.f, 0.f);
                        owned = true;
                        cur   = __shfl_sync(FULL, d_r, e);
                    }
                    float wt  = __shfl_sync(FULL, w_r, e);
                    float2 lo = __half22float2(*(__half2*)&v[j].x);
                    float2 hi = __half22float2(*(__half2*)&v[j].y);
                    acc.x += wt * lo.x;
                    acc.y += wt * lo.y;
                    acc.z += wt * hi.x;
                    acc.w += wt * hi.y;
                }
            }
        }
    } else {
        // cold tail path (unused for E % EPW == 0, kept for generality)
        long long end = E;
        for (long long e = base; e < end; ++e) {
            int d = dst[e];
            if (d != cur) {
                flush_seg(out, cur, lane, acc, owned);
                acc   = make_float4(0.f, 0.f, 0.f, 0.f);
                owned = true;
                cur   = d;
            }
            uint2  v  = XFr[(unsigned)src[e] * 32u + lane];
            float  wt = w[e];
            float2 lo = __half22float2(*(__half2*)&v.x);
            float2 hi = __half22float2(*(__half2*)&v.y);
            acc.x += wt * lo.x;
            acc.y += wt * lo.y;
            acc.z += wt * hi.x;
            acc.w += wt * hi.y;
        }
    }

    // final flush: segment may continue into next chunk -> reduction
    red_v4(out + (size_t)cur * NF + lane * 4, acc);
}

// ---------------------------------------------------------------------------
extern "C" void kernel_launch(void* const* d_in, const int* in_sizes, int n_in,
                              void* d_out, int out_size)
{
    const float* x    = (const float*)d_in[0];
    const float* f    = (const float*)d_in[1];
    const int*   esrc = (const int*)d_in[2];
    const int*   edst = (const int*)d_in[3];
    const float* ew   = (const float*)d_in[4];
    float*       out  = (float*)d_out;

    const int M = in_sizes[0] / NF;   // 100000
    const int E = in_sizes[2];        // 3200000

    cudaMemsetAsync(d_out, 0, (size_t)out_size * sizeof(float), 0);

    gemm_tf32<<<(M + 63) / 64, 256>>>(x, f, M);

    int warps  = (E + EPW - 1) / EPW;
    int blocks = (warps * 32 + 255) / 256;
    agg_kernel<<<blocks, 256>>>(esrc, edst, ew, out, E);
}

// round 16
// speedup vs baseline: 1.7111x; 1.0022x over previous
#include <cuda_runtime.h>
#include <cuda_fp16.h>
#include <cstdint>

// ---------------------------------------------------------------------------
// KipfAndWellingConv: out = segment_sum(w_e * (x @ F)[src_e], dst_e)
// R14..R16 (resubmit; broker timeouts): GEMM restructured to BM=128/BK=16
// (8-tile cp.async pipeline, warp tile 32x64). Agg unchanged from R13.
// ---------------------------------------------------------------------------

#define NF 128
#define EPW 128              // edges per warp (3.2M % 128 == 0)
#define FULL 0xFFFFFFFFu

__device__ __half g_XFh[100000 * NF];   // XF scratch, fp16 (25.6 MB)

// ---------------------------------------------------------------------------
__device__ __forceinline__ float to_tf32(float x)
{
    float r;
    asm("cvt.rna.tf32.f32 %0, %1;" : "=f"(r) : "f"(x));
    return r;
}

__device__ __forceinline__ void mma_tf32(float* d, const uint32_t* a, const uint32_t* b)
{
    asm volatile(
        "mma.sync.aligned.m16n8k8.row.col.f32.tf32.tf32.f32 "
        "{%0,%1,%2,%3}, {%4,%5,%6,%7}, {%8,%9}, {%0,%1,%2,%3};\n"
        : "+f"(d[0]), "+f"(d[1]), "+f"(d[2]), "+f"(d[3])
        : "r"(a[0]), "r"(a[1]), "r"(a[2]), "r"(a[3]), "r"(b[0]), "r"(b[1]));
}

__device__ __forceinline__ void cp16(uint32_t smem_addr, const void* gptr, bool pred)
{
    asm volatile("cp.async.ca.shared.global [%0], [%1], 16, %2;\n"
                 :: "r"(smem_addr), "l"(gptr), "r"(pred ? 16 : 0));
}
__device__ __forceinline__ void cp_commit()
{
    asm volatile("cp.async.commit_group;\n");
}
template <int N>
__device__ __forceinline__ void cp_wait()
{
    asm volatile("cp.async.wait_group %0;\n" :: "n"(N));
}

// GEMM: XF[M,128] = X[M,128] @ F[128,128], tf32 tensor cores, fp16 output.
// Block tile 128x128, BK=16, 8 k-tiles, 2-stage cp.async double buffer.
// 8 warps, warp tile 32x64 (2x8 m16n8k8 frags). RNA tf32 cvt on fragments.
__global__ __launch_bounds__(256)
void gemm_tf32(const float* __restrict__ X, const float* __restrict__ F, int M)
{
    __shared__ float As[2][128][20];   // 128x16 tile, pad->20 (bank=4g+t, CF)
    __shared__ float Bs[2][16][136];   // 16x128 tile, pad->136 (bank=8t+g, CF)

    const int tid  = threadIdx.x;
    const int row0 = blockIdx.x * 128;
    const int wid  = tid >> 5;
    const int lane = tid & 31;
    const int g    = lane >> 2;          // 0..7
    const int t    = lane & 3;           // 0..3
    const int wm0  = (wid >> 1) * 32;    // 0/32/64/96
    const int wn0  = (wid & 1) * 64;     // 0/64

    // per-thread load coords: A tile 128x16 = 512 f4 (2/thr), row = i4/4
    const int ar0 = (tid + 0)   >> 2, ac0 = ((tid + 0)   & 3) * 4;
    const int ar1 = (tid + 256) >> 2, ac1 = ((tid + 256) & 3) * 4;

    auto load_stage = [&](int kt, int buf) {
        cp16(__cvta_generic_to_shared(&As[buf][ar0][ac0]),
             X + (size_t)(row0 + ar0) * NF + kt * 16 + ac0, row0 + ar0 < M);
        cp16(__cvta_generic_to_shared(&As[buf][ar1][ac1]),
             X + (size_t)(row0 + ar1) * NF + kt * 16 + ac1, row0 + ar1 < M);
        // B tile 16x128 = 512 f4 (2/thr)
#pragma unroll
        for (int p = 0; p < 2; ++p) {
            int i4 = tid + p * 256;
            int r  = i4 >> 5;
            int c  = (i4 & 31) * 4;
            cp16(__cvta_generic_to_shared(&Bs[buf][r][c]),
                 F + (size_t)(kt * 16 + r) * NF + c, true);
        }
    };

    float d[2][8][4];
#pragma unroll
    for (int i = 0; i < 2; ++i)
#pragma unroll
        for (int j = 0; j < 8; ++j)
#pragma unroll
            for (int k = 0; k < 4; ++k) d[i][j][k] = 0.f;

    load_stage(0, 0);
    cp_commit();

    for (int kt = 0; kt < 8; ++kt) {
        const int buf = kt & 1;
        if (kt < 7) {
            load_stage(kt + 1, buf ^ 1);
            cp_commit();
            cp_wait<1>();
        } else {
            cp_wait<0>();
        }
        __syncthreads();

#pragma unroll
        for (int k8 = 0; k8 < 2; ++k8) {
            const int kb = k8 * 8;
            uint32_t a[2][4], b[8][2];
#pragma unroll
            for (int im = 0; im < 2; ++im) {
                int rb = wm0 + im * 16 + g;
                a[im][0] = __float_as_uint(to_tf32(As[buf][rb][kb + t]));
                a[im][1] = __float_as_uint(to_tf32(As[buf][rb + 8][kb + t]));
                a[im][2] = __float_as_uint(to_tf32(As[buf][rb][kb + t + 4]));
                a[im][3] = __float_as_uint(to_tf32(As[buf][rb + 8][kb + t + 4]));
            }
#pragma unroll
            for (int jn = 0; jn < 8; ++jn) {
                int cb = wn0 + jn * 8 + g;
                b[jn][0] = __float_as_uint(to_tf32(Bs[buf][kb + t][cb]));
                b[jn][1] = __float_as_uint(to_tf32(Bs[buf][kb + t + 4][cb]));
            }
#pragma unroll
            for (int im = 0; im < 2; ++im)
#pragma unroll
                for (int jn = 0; jn < 8; ++jn)
                    mma_tf32(d[im][jn], a[im], b[jn]);
        }
        __syncthreads();
    }

#pragma unroll
    for (int im = 0; im < 2; ++im) {
#pragma unroll
        for (int half = 0; half < 2; ++half) {
            int grow = row0 + wm0 + im * 16 + half * 8 + g;
            if (grow < M) {
#pragma unroll
                for (int jn = 0; jn < 8; ++jn) {
                    float2 v = make_float2(d[im][jn][half * 2],
                                           d[im][jn][half * 2 + 1]);
                    __half2 h = __float22half2_rn(v);
                    *(__half2*)(g_XFh + (size_t)grow * NF + wn0 + jn * 8 + t * 2) = h;
                }
            }
        }
    }
}

// ---------------------------------------------------------------------------
__device__ __forceinline__ void red_v4(float* o, const float4& a)
{
    asm volatile("red.global.add.v4.f32 [%0], {%1, %2, %3, %4};\n"
                 :: "l"(o), "f"(a.x), "f"(a.y), "f"(a.z), "f"(a.w) : "memory");
}

__device__ __forceinline__ void flush_seg(float* __restrict__ out, int node,
                                          int lane, const float4& acc, bool owned)
{
    float* o = out + (size_t)node * NF + lane * 4;
    if (owned) {
        *(float4*)o = acc;          // exclusive interior segment
    } else {
        red_v4(o, acc);             // one REDG.128 per lane
    }
}

// Aggregation (unchanged from R13): warp per EPW edges; lane-parallel
// metadata, ballot boundary mask, shfl broadcast, 8-deep gather batches,
// vectorized reduction flushes.
__global__ __launch_bounds__(256)
void agg_kernel(const int* __restrict__ src,
                const int* __restrict__ dst,
                const float* __restrict__ w,
                float* __restrict__ out, int E)
{
    const int gw   = (blockIdx.x * blockDim.x + threadIdx.x) >> 5;
    const int lane = threadIdx.x & 31;

    const long long base = (long long)gw * EPW;
    if (base >= E) return;

    const uint2* __restrict__ XFr = (const uint2*)g_XFh;   // 32 uint2 / row

    float4 acc = make_float4(0.f, 0.f, 0.f, 0.f);
    int  cur   = dst[base];
    bool owned = false;
    int  prev_last = cur;

    if (base + EPW <= E) {
#pragma unroll 1
        for (int b = 0; b < EPW / 32; ++b) {
            const long long t0 = base + b * 32;
            int   s_r = src[t0 + lane];
            int   d_r = dst[t0 + lane];
            float w_r = w[t0 + lane];

            int dprev = __shfl_up_sync(FULL, d_r, 1);
            if (lane == 0) dprev = prev_last;
            unsigned bmask = __ballot_sync(FULL, d_r != dprev);
            prev_last = __shfl_sync(FULL, d_r, 31);

#pragma unroll
            for (int q = 0; q < 4; ++q) {
                uint2 v[8];
#pragma unroll
                for (int j = 0; j < 8; ++j) {
                    int sj = __shfl_sync(FULL, s_r, q * 8 + j);
                    v[j] = __ldg(&XFr[(unsigned)sj * 32u + lane]);
                }
#pragma unroll
                for (int j = 0; j < 8; ++j) {
                    const int e = q * 8 + j;
                    if (bmask & (1u << e)) {
                        flush_seg(out, cur, lane, acc, owned);
                        acc   = make_float4(0.f, 0.f, 0.f, 0.f);
                        owned = true;
                        cur   = __shfl_sync(FULL, d_r, e);
                    }
                    float wt  = __shfl_sync(FULL, w_r, e);
                    float2 lo = __half22float2(*(__half2*)&v[j].x);
                    float2 hi = __half22float2(*(__half2*)&v[j].y);
                    acc.x += wt * lo.x;
                    acc.y += wt * lo.y;
                    acc.z += wt * hi.x;
                    acc.w += wt * hi.y;
                }
            }
        }
    } else {
        // cold tail path (unused for E % EPW == 0, kept for generality)
        long long end = E;
        for (long long e = base; e < end; ++e) {
            int d = dst[e];
            if (d != cur) {
                flush_seg(out, cur, lane, acc, owned);
                acc   = make_float4(0.f, 0.f, 0.f, 0.f);
                owned = true;
                cur   = d;
            }
            uint2  v  = XFr[(unsigned)src[e] * 32u + lane];
            float  wt = w[e];
            float2 lo = __half22float2(*(__half2*)&v.x);
            float2 hi = __half22float2(*(__half2*)&v.y);
            acc.x += wt * lo.x;
            acc.y += wt * lo.y;
            acc.z += wt * hi.x;
            acc.w += wt * hi.y;
        }
    }

    // final flush: segment may continue into next chunk -> reduction
    red_v4(out + (size_t)cur * NF + lane * 4, acc);
}

// ---------------------------------------------------------------------------
extern "C" void kernel_launch(void* const* d_in, const int* in_sizes, int n_in,
                              void* d_out, int out_size)
{
    const float* x    = (const float*)d_in[0];
    const float* f    = (const float*)d_in[1];
    const int*   esrc = (const int*)d_in[2];
    const int*   edst = (const int*)d_in[3];
    const float* ew   = (const float*)d_in[4];
    float*       out  = (float*)d_out;

    const int M = in_sizes[0] / NF;   // 100000
    const int E = in_sizes[2];        // 3200000

    cudaMemsetAsync(d_out, 0, (size_t)out_size * sizeof(float), 0);

    gemm_tf32<<<(M + 127) / 128, 256>>>(x, f, M);

    int warps  = (E + EPW - 1) / EPW;
    int blocks = (warps * 32 + 255) / 256;
    agg_kernel<<<blocks, 256>>>(esrc, edst, ew, out, E);
}